// round 1
// baseline (speedup 1.0000x reference)
#include <cuda_runtime.h>

#define N_NODES  50000
#define E_EDGES  400000
#define G_GRAPHS 64
#define H_DIM    300
#define L_DIM    100
#define TE       64
#define KC       20
#define HP       304
#define BP       132
#define NTHREADS 256

// Scratch: node features after edge layer 0 / 1 (20 MB each)
__device__ float g_h1[N_NODES * L_DIM];
__device__ float g_h2[N_NODES * L_DIM];

__global__ void zero_kernel(float* __restrict__ p, int n) {
    int i = blockIdx.x * blockDim.x + threadIdx.x;
    int stride = gridDim.x * blockDim.x;
    for (; i < n; i += stride) p[i] = 0.f;
}

// One [64 x NCOLS] GEMM tile: D = act(A[64 x K] @ W[K x NCOLS] + bias)
// A in smem (pitch AP), W streamed from global through smem chunks, D to smem
// (pitch HP) or clamped atomicMax-scattered to global (per-edge dst rows).
template<int KCHUNKS, int KTRUE, int NCOLS, int AP, bool RELU, bool TO_GLOBAL>
__device__ __forceinline__ void gemm_tile(
    const float* As, const float* __restrict__ W, const float* __restrict__ bias,
    float* Ds, float* s_B, const int* s_dst, int e0, float* OUT)
{
    const int tid = threadIdx.x;
    const int cg = tid & 31;   // column group (TN=4 cols)
    const int eg = tid >> 5;   // edge group (TM=8 edges)
    constexpr int NB = (NCOLS + 127) / 128;

    for (int nb = 0; nb < NB; nb++) {
        const int nbase = nb * 128;
        float acc[8][4];
#pragma unroll
        for (int i = 0; i < 8; i++)
#pragma unroll
            for (int j = 0; j < 4; j++) acc[i][j] = 0.f;

        for (int kc = 0; kc < KCHUNKS; kc++) {
            __syncthreads();
            // stage B chunk [KC x 128] (zero-padded out of range)
#pragma unroll 4
            for (int idx = tid; idx < KC * 128; idx += NTHREADS) {
                int kk = idx >> 7, c = idx & 127;
                int k = kc * KC + kk, col = nbase + c;
                float v = 0.f;
                if (k < KTRUE && col < NCOLS) v = W[k * NCOLS + col];
                s_B[kk * BP + c] = v;
            }
            __syncthreads();
            const float* Arow = As + kc * KC;
#pragma unroll
            for (int kk = 0; kk < KC; kk++) {
                float a[8];
#pragma unroll
                for (int i = 0; i < 8; i++) a[i] = Arow[(eg * 8 + i) * AP + kk];
                float4 b = *(const float4*)(s_B + kk * BP + cg * 4);
#pragma unroll
                for (int i = 0; i < 8; i++) {
                    acc[i][0] = fmaf(a[i], b.x, acc[i][0]);
                    acc[i][1] = fmaf(a[i], b.y, acc[i][1]);
                    acc[i][2] = fmaf(a[i], b.z, acc[i][2]);
                    acc[i][3] = fmaf(a[i], b.w, acc[i][3]);
                }
            }
        }
        // epilogue
#pragma unroll
        for (int j = 0; j < 4; j++) {
            int c = nbase + cg * 4 + j;
            if (c < NCOLS) {
                float bv = bias[c];
#pragma unroll
                for (int i = 0; i < 8; i++) {
                    int e = eg * 8 + i;
                    float v = acc[i][j] + bv;
                    if (RELU || TO_GLOBAL) v = fmaxf(v, 0.f);
                    if (TO_GLOBAL) {
                        // relu(segment_max) == atomicMax over clamped msgs into
                        // zero-init buffer; nonneg float order == int order.
                        if (e0 + e < E_EDGES)
                            atomicMax(reinterpret_cast<int*>(OUT) + s_dst[e] * NCOLS + c,
                                      __float_as_int(v));
                    } else {
                        Ds[e * HP + c] = v;
                    }
                }
            }
        }
    }
}

// Fused per-edge MLP: gather [x_i, x_j - x_i] -> 2*CIN -> 300 -> 300 -> 100
// -> clamped scatter-max into OUT[dst].
template<int CIN>
__global__ void __launch_bounds__(NTHREADS, 1)
edge_mlp_kernel(const float* __restrict__ X,
                const int* __restrict__ src, const int* __restrict__ dst,
                const float* __restrict__ W1, const float* __restrict__ B1,
                const float* __restrict__ W2, const float* __restrict__ B2,
                const float* __restrict__ W3, const float* __restrict__ B3,
                float* __restrict__ OUT)
{
    constexpr int KIN  = 2 * CIN;
    constexpr int KCH1 = (KIN + KC - 1) / KC;
    constexpr int INP  = KCH1 * KC;   // padded input pitch (20 or 200)

    extern __shared__ float smem[];
    float* s_h1 = smem;                 // [64][304] hidden1
    float* s_u  = smem + TE * HP;       // union: input [64][INP] then hidden2 [64][304]
    float* s_B  = s_u + TE * HP;        // [KC][132] weight chunk
    int* s_src  = (int*)(s_B + KC * BP);
    int* s_dst  = s_src + TE;

    const int tid = threadIdx.x;
    const int e0  = blockIdx.x * TE;

    if (tid < TE) {
        int e = min(e0 + tid, E_EDGES - 1);
        s_src[tid] = src[e];
        s_dst[tid] = dst[e];
    }
    __syncthreads();

    // gather: s_u[e][0:CIN] = x_i, s_u[e][CIN:2CIN] = x_j - x_i
    for (int idx = tid; idx < TE * CIN; idx += NTHREADS) {
        int e = idx / CIN, k = idx - e * CIN;
        float xi = X[s_dst[e] * CIN + k];
        float xj = X[s_src[e] * CIN + k];
        s_u[e * INP + k] = xi;
        s_u[e * INP + CIN + k] = xj - xi;
    }
    if (INP > KIN) {
        for (int idx = tid; idx < TE * (INP - KIN); idx += NTHREADS) {
            int e = idx / (INP - KIN), k = KIN + (idx - e * (INP - KIN));
            s_u[e * INP + k] = 0.f;
        }
    }
    // (gemm_tile's leading __syncthreads orders the gather writes)

    gemm_tile<KCH1, KIN, H_DIM, INP, true, false>(s_u,  W1, B1, s_h1, s_B, s_dst, e0, nullptr);
    gemm_tile<H_DIM / KC, H_DIM, H_DIM, HP, true, false>(s_h1, W2, B2, s_u, s_B, s_dst, e0, nullptr);
    gemm_tile<H_DIM / KC, H_DIM, L_DIM, HP, false, true>(s_u,  W3, B3, nullptr, s_B, s_dst, e0, OUT);
}

// One block per graph: contiguous segment (batch is sorted) -> add/mean/max
// pooling -> 302 -> 100 -> 100 -> 2 MLP.
__global__ void pool_mlp_kernel(const float* __restrict__ H2,
                                const int* __restrict__ batch,
                                const float* __restrict__ u,
                                const float* __restrict__ w1, const float* __restrict__ b1,
                                const float* __restrict__ w2, const float* __restrict__ b2,
                                const float* __restrict__ w3, const float* __restrict__ b3,
                                float* __restrict__ out)
{
    const int g = blockIdx.x;
    const int t = threadIdx.x;
    __shared__ float p[304];
    __shared__ float q1[100];
    __shared__ float q2[100];

    int s, e2;
    { int a = 0, b = N_NODES; while (a < b) { int m = (a + b) >> 1; if (batch[m] < g) a = m + 1; else b = m; } s = a; }
    { int a = 0, b = N_NODES; while (a < b) { int m = (a + b) >> 1; if (batch[m] < g + 1) a = m + 1; else b = m; } e2 = a; }
    int cnt = e2 - s;

    if (t < L_DIM) {
        float sm = 0.f, mx = 0.f;
        for (int i = s; i < e2; i++) {
            float v = H2[i * L_DIM + t];
            sm += v;
            mx = fmaxf(mx, v);
        }
        p[t] = sm;
        p[L_DIM + t] = sm / fmaxf((float)cnt, 1.0f);
        p[2 * L_DIM + t] = (cnt > 0) ? mx : 0.f;
    }
    if (t < 2) p[3 * L_DIM + t] = u[g * 2 + t];
    __syncthreads();

    if (t < L_DIM) {
        float acc = b1[t];
        for (int k = 0; k < 3 * L_DIM + 2; k++) acc = fmaf(p[k], w1[k * L_DIM + t], acc);
        q1[t] = fmaxf(acc, 0.f);
    }
    __syncthreads();
    if (t < L_DIM) {
        float acc = b2[t];
        for (int k = 0; k < L_DIM; k++) acc = fmaf(q1[k], w2[k * L_DIM + t], acc);
        q2[t] = fmaxf(acc, 0.f);
    }
    __syncthreads();
    if (t < 2) {
        float acc = b3[t];
        for (int k = 0; k < L_DIM; k++) acc = fmaf(q2[k], w3[k * 2 + t], acc);
        out[g * 2 + t] = acc;
    }
}

extern "C" void kernel_launch(void* const* d_in, const int* in_sizes, int n_in,
                              void* d_out, int out_size)
{
    const float* x     = (const float*)d_in[0];
    const int*   ei    = (const int*)d_in[1];
    const int*   batch = (const int*)d_in[2];
    const float* u     = (const float*)d_in[3];
    const float* l0w1  = (const float*)d_in[4];
    const float* l0b1  = (const float*)d_in[5];
    const float* l0w2  = (const float*)d_in[6];
    const float* l0b2  = (const float*)d_in[7];
    const float* l0w3  = (const float*)d_in[8];
    const float* l0b3  = (const float*)d_in[9];
    const float* l1w1  = (const float*)d_in[10];
    const float* l1b1  = (const float*)d_in[11];
    const float* l1w2  = (const float*)d_in[12];
    const float* l1b2  = (const float*)d_in[13];
    const float* l1w3  = (const float*)d_in[14];
    const float* l1b3  = (const float*)d_in[15];
    const float* lw1   = (const float*)d_in[16];
    const float* lb1   = (const float*)d_in[17];
    const float* lw2   = (const float*)d_in[18];
    const float* lb2   = (const float*)d_in[19];
    const float* lw3   = (const float*)d_in[20];
    const float* lb3   = (const float*)d_in[21];
    float* out = (float*)d_out;

    const int* src = ei;
    const int* dst = ei + E_EDGES;

    float *h1p, *h2p;
    cudaGetSymbolAddress((void**)&h1p, g_h1);
    cudaGetSymbolAddress((void**)&h2p, g_h2);

    const int smem_bytes = (TE * HP * 2 + KC * BP) * (int)sizeof(float) + 2 * TE * (int)sizeof(int);
    cudaFuncSetAttribute(edge_mlp_kernel<7>,   cudaFuncAttributeMaxDynamicSharedMemorySize, smem_bytes);
    cudaFuncSetAttribute(edge_mlp_kernel<100>, cudaFuncAttributeMaxDynamicSharedMemorySize, smem_bytes);

    zero_kernel<<<304, 256>>>(h1p, N_NODES * L_DIM);
    zero_kernel<<<304, 256>>>(h2p, N_NODES * L_DIM);

    const int nblk = (E_EDGES + TE - 1) / TE;
    edge_mlp_kernel<7><<<nblk, NTHREADS, smem_bytes>>>(
        x, src, dst, l0w1, l0b1, l0w2, l0b2, l0w3, l0b3, h1p);
    edge_mlp_kernel<100><<<nblk, NTHREADS, smem_bytes>>>(
        h1p, src, dst, l1w1, l1b1, l1w2, l1b2, l1w3, l1b3, h2p);
    pool_mlp_kernel<<<G_GRAPHS, 128>>>(
        h2p, batch, u, lw1, lb1, lw2, lb2, lw3, lb3, out);
}

// round 2
// speedup vs baseline: 1.0647x; 1.0647x over previous
#include <cuda_runtime.h>
#include <cstdint>

#define N_NODES  50000
#define E_EDGES  400000
#define G_GRAPHS 64
#define H_DIM    300
#define L_DIM    100
#define TE       64
#define KC       20
#define HP       304
#define BP       132
#define NTHREADS 256

// Scratch: node features after edge layer 0 / 1 (20 MB each)
__device__ float g_h1[N_NODES * L_DIM];
__device__ float g_h2[N_NODES * L_DIM];

__global__ void zero_kernel(float* __restrict__ p, int n) {
    int i = blockIdx.x * blockDim.x + threadIdx.x;
    int stride = gridDim.x * blockDim.x;
    for (; i < n; i += stride) p[i] = 0.f;
}

// ---- packed fp32x2 helpers (Blackwell FFMA2 path, PTX-only) ----
__device__ __forceinline__ uint64_t f32x2_pack(float x, float y) {
    uint64_t r;
    asm("mov.b64 %0, {%1, %2};" : "=l"(r) : "f"(x), "f"(y));
    return r;
}
__device__ __forceinline__ uint64_t f32x2_fma(uint64_t a, uint64_t b, uint64_t c) {
    uint64_t d;
    asm("fma.rn.f32x2 %0, %1, %2, %3;" : "=l"(d) : "l"(a), "l"(b), "l"(c));
    return d;
}
__device__ __forceinline__ void f32x2_unpack(uint64_t v, float& x, float& y) {
    asm("mov.b64 {%0, %1}, %2;" : "=f"(x), "=f"(y) : "l"(v));
}

// One [64 x NCOLS] GEMM tile: D = act(A[64 x K] @ W[K x NCOLS] + bias)
// A in smem (pitch AP), W streamed through smem chunks, packed-f32x2 FFMA2
// microkernel (8 edges x 4 cols per thread as 8x2 f32x2 accumulators).
template<int KCHUNKS, int KTRUE, int NCOLS, int AP, bool RELU, bool TO_GLOBAL>
__device__ __forceinline__ void gemm_tile(
    const float* As, const float* __restrict__ W, const float* __restrict__ bias,
    float* Ds, float* s_B, const int* s_dst, int e0, float* OUT)
{
    const int tid = threadIdx.x;
    const int cg = tid & 31;   // column group (4 cols)
    const int eg = tid >> 5;   // edge group (8 edges)
    constexpr int NB = (NCOLS + 127) / 128;

    for (int nb = 0; nb < NB; nb++) {
        const int nbase = nb * 128;
        uint64_t acc[8][2];
#pragma unroll
        for (int i = 0; i < 8; i++) { acc[i][0] = 0ull; acc[i][1] = 0ull; }

        for (int kc = 0; kc < KCHUNKS; kc++) {
            __syncthreads();
            // stage B chunk [KC x 128] (zero-padded out of range)
#pragma unroll 4
            for (int idx = tid; idx < KC * 128; idx += NTHREADS) {
                int kk = idx >> 7, c = idx & 127;
                int k = kc * KC + kk, col = nbase + c;
                float v = 0.f;
                if (k < KTRUE && col < NCOLS) v = W[k * NCOLS + col];
                s_B[kk * BP + c] = v;
            }
            __syncthreads();
            const float* Arow = As + kc * KC;
#pragma unroll
            for (int kk0 = 0; kk0 < KC; kk0 += 4) {
                float4 aq[8];
#pragma unroll
                for (int i = 0; i < 8; i++)
                    aq[i] = *(const float4*)(Arow + (eg * 8 + i) * AP + kk0);
#pragma unroll
                for (int t = 0; t < 4; t++) {
                    float4 bq = *(const float4*)(s_B + (kk0 + t) * BP + cg * 4);
                    uint64_t b01 = f32x2_pack(bq.x, bq.y);
                    uint64_t b23 = f32x2_pack(bq.z, bq.w);
#pragma unroll
                    for (int i = 0; i < 8; i++) {
                        float av = (t == 0) ? aq[i].x : (t == 1) ? aq[i].y
                                 : (t == 2) ? aq[i].z : aq[i].w;
                        uint64_t ap = f32x2_pack(av, av);
                        acc[i][0] = f32x2_fma(ap, b01, acc[i][0]);
                        acc[i][1] = f32x2_fma(ap, b23, acc[i][1]);
                    }
                }
            }
        }
        // epilogue (NCOLS is a multiple of 4 -> whole float4 in/out of range)
        const int c0 = nbase + cg * 4;
        if (c0 < NCOLS) {
            float4 bv = *(const float4*)(bias + c0);
#pragma unroll
            for (int i = 0; i < 8; i++) {
                float v0, v1, v2, v3;
                f32x2_unpack(acc[i][0], v0, v1);
                f32x2_unpack(acc[i][1], v2, v3);
                v0 += bv.x; v1 += bv.y; v2 += bv.z; v3 += bv.w;
                if (RELU || TO_GLOBAL) {
                    v0 = fmaxf(v0, 0.f); v1 = fmaxf(v1, 0.f);
                    v2 = fmaxf(v2, 0.f); v3 = fmaxf(v3, 0.f);
                }
                int e = eg * 8 + i;
                if (TO_GLOBAL) {
                    // relu(segment_max) == atomicMax over clamped msgs into
                    // zero-init buffer; nonneg float order == int order.
                    if (e0 + e < E_EDGES) {
                        int* o = reinterpret_cast<int*>(OUT) + s_dst[e] * NCOLS + c0;
                        atomicMax(o + 0, __float_as_int(v0));
                        atomicMax(o + 1, __float_as_int(v1));
                        atomicMax(o + 2, __float_as_int(v2));
                        atomicMax(o + 3, __float_as_int(v3));
                    }
                } else {
                    *(float4*)(Ds + e * HP + c0) = make_float4(v0, v1, v2, v3);
                }
            }
        }
    }
}

// Fused per-edge MLP: gather [x_i, x_j - x_i] -> 2*CIN -> 300 -> 300 -> 100
// -> clamped scatter-max into OUT[dst].
template<int CIN>
__global__ void __launch_bounds__(NTHREADS, 1)
edge_mlp_kernel(const float* __restrict__ X,
                const int* __restrict__ src, const int* __restrict__ dst,
                const float* __restrict__ W1, const float* __restrict__ B1,
                const float* __restrict__ W2, const float* __restrict__ B2,
                const float* __restrict__ W3, const float* __restrict__ B3,
                float* __restrict__ OUT)
{
    constexpr int KIN  = 2 * CIN;
    constexpr int KCH1 = (KIN + KC - 1) / KC;
    constexpr int INP  = KCH1 * KC;   // padded input pitch (20 or 200)

    extern __shared__ float smem[];
    float* s_h1 = smem;                 // [64][304] hidden1
    float* s_u  = smem + TE * HP;       // union: input [64][INP] then hidden2 [64][304]
    float* s_B  = s_u + TE * HP;        // [KC][132] weight chunk
    int* s_src  = (int*)(s_B + KC * BP);
    int* s_dst  = s_src + TE;

    const int tid = threadIdx.x;
    const int e0  = blockIdx.x * TE;

    if (tid < TE) {
        int e = min(e0 + tid, E_EDGES - 1);
        s_src[tid] = src[e];
        s_dst[tid] = dst[e];
    }
    __syncthreads();

    // gather: s_u[e][0:CIN] = x_i, s_u[e][CIN:2CIN] = x_j - x_i
    for (int idx = tid; idx < TE * CIN; idx += NTHREADS) {
        int e = idx / CIN, k = idx - e * CIN;
        float xi = X[s_dst[e] * CIN + k];
        float xj = X[s_src[e] * CIN + k];
        s_u[e * INP + k] = xi;
        s_u[e * INP + CIN + k] = xj - xi;
    }
    if (INP > KIN) {
        for (int idx = tid; idx < TE * (INP - KIN); idx += NTHREADS) {
            int e = idx / (INP - KIN), k = KIN + (idx - e * (INP - KIN));
            s_u[e * INP + k] = 0.f;
        }
    }
    // (gemm_tile's leading __syncthreads orders the gather writes)

    gemm_tile<KCH1, KIN, H_DIM, INP, true, false>(s_u,  W1, B1, s_h1, s_B, s_dst, e0, nullptr);
    gemm_tile<H_DIM / KC, H_DIM, H_DIM, HP, true, false>(s_h1, W2, B2, s_u, s_B, s_dst, e0, nullptr);
    gemm_tile<H_DIM / KC, H_DIM, L_DIM, HP, false, true>(s_u,  W3, B3, nullptr, s_B, s_dst, e0, OUT);
}

// One block per graph: contiguous segment (batch is sorted) -> add/mean/max
// pooling -> 302 -> 100 -> 100 -> 2 MLP.
__global__ void pool_mlp_kernel(const float* __restrict__ H2,
                                const int* __restrict__ batch,
                                const float* __restrict__ u,
                                const float* __restrict__ w1, const float* __restrict__ b1,
                                const float* __restrict__ w2, const float* __restrict__ b2,
                                const float* __restrict__ w3, const float* __restrict__ b3,
                                float* __restrict__ out)
{
    const int g = blockIdx.x;
    const int t = threadIdx.x;
    __shared__ float p[304];
    __shared__ float q1[100];
    __shared__ float q2[100];

    int s, e2;
    { int a = 0, b = N_NODES; while (a < b) { int m = (a + b) >> 1; if (batch[m] < g) a = m + 1; else b = m; } s = a; }
    { int a = 0, b = N_NODES; while (a < b) { int m = (a + b) >> 1; if (batch[m] < g + 1) a = m + 1; else b = m; } e2 = a; }
    int cnt = e2 - s;

    if (t < L_DIM) {
        float sm = 0.f, mx = 0.f;
        for (int i = s; i < e2; i++) {
            float v = H2[i * L_DIM + t];
            sm += v;
            mx = fmaxf(mx, v);
        }
        p[t] = sm;
        p[L_DIM + t] = sm / fmaxf((float)cnt, 1.0f);
        p[2 * L_DIM + t] = (cnt > 0) ? mx : 0.f;
    }
    if (t < 2) p[3 * L_DIM + t] = u[g * 2 + t];
    __syncthreads();

    if (t < L_DIM) {
        float acc = b1[t];
        for (int k = 0; k < 3 * L_DIM + 2; k++) acc = fmaf(p[k], w1[k * L_DIM + t], acc);
        q1[t] = fmaxf(acc, 0.f);
    }
    __syncthreads();
    if (t < L_DIM) {
        float acc = b2[t];
        for (int k = 0; k < L_DIM; k++) acc = fmaf(q1[k], w2[k * L_DIM + t], acc);
        q2[t] = fmaxf(acc, 0.f);
    }
    __syncthreads();
    if (t < 2) {
        float acc = b3[t];
        for (int k = 0; k < L_DIM; k++) acc = fmaf(q2[k], w3[k * 2 + t], acc);
        out[g * 2 + t] = acc;
    }
}

extern "C" void kernel_launch(void* const* d_in, const int* in_sizes, int n_in,
                              void* d_out, int out_size)
{
    const float* x     = (const float*)d_in[0];
    const int*   ei    = (const int*)d_in[1];
    const int*   batch = (const int*)d_in[2];
    const float* u     = (const float*)d_in[3];
    const float* l0w1  = (const float*)d_in[4];
    const float* l0b1  = (const float*)d_in[5];
    const float* l0w2  = (const float*)d_in[6];
    const float* l0b2  = (const float*)d_in[7];
    const float* l0w3  = (const float*)d_in[8];
    const float* l0b3  = (const float*)d_in[9];
    const float* l1w1  = (const float*)d_in[10];
    const float* l1b1  = (const float*)d_in[11];
    const float* l1w2  = (const float*)d_in[12];
    const float* l1b2  = (const float*)d_in[13];
    const float* l1w3  = (const float*)d_in[14];
    const float* l1b3  = (const float*)d_in[15];
    const float* lw1   = (const float*)d_in[16];
    const float* lb1   = (const float*)d_in[17];
    const float* lw2   = (const float*)d_in[18];
    const float* lb2   = (const float*)d_in[19];
    const float* lw3   = (const float*)d_in[20];
    const float* lb3   = (const float*)d_in[21];
    float* out = (float*)d_out;

    const int* src = ei;
    const int* dst = ei + E_EDGES;

    float *h1p, *h2p;
    cudaGetSymbolAddress((void**)&h1p, g_h1);
    cudaGetSymbolAddress((void**)&h2p, g_h2);

    const int smem_bytes = (TE * HP * 2 + KC * BP) * (int)sizeof(float) + 2 * TE * (int)sizeof(int);
    cudaFuncSetAttribute(edge_mlp_kernel<7>,   cudaFuncAttributeMaxDynamicSharedMemorySize, smem_bytes);
    cudaFuncSetAttribute(edge_mlp_kernel<100>, cudaFuncAttributeMaxDynamicSharedMemorySize, smem_bytes);

    zero_kernel<<<304, 256>>>(h1p, N_NODES * L_DIM);
    zero_kernel<<<304, 256>>>(h2p, N_NODES * L_DIM);

    const int nblk = (E_EDGES + TE - 1) / TE;
    edge_mlp_kernel<7><<<nblk, NTHREADS, smem_bytes>>>(
        x, src, dst, l0w1, l0b1, l0w2, l0b2, l0w3, l0b3, h1p);
    edge_mlp_kernel<100><<<nblk, NTHREADS, smem_bytes>>>(
        h1p, src, dst, l1w1, l1b1, l1w2, l1b2, l1w3, l1b3, h2p);
    pool_mlp_kernel<<<G_GRAPHS, 128>>>(
        h2p, batch, u, lw1, lb1, lw2, lb2, lw3, lb3, out);
}

// round 3
// speedup vs baseline: 1.3996x; 1.3145x over previous
#include <cuda_runtime.h>
#include <cstdint>

#define N_NODES  50000
#define E_EDGES  400000
#define G_GRAPHS 64
#define H_DIM    300
#define L_DIM    100
#define TE       64
#define KC       20
#define ATP      68      // transposed activation pitch (floats per k-row)
#define BPD      260     // duplicated-B pitch (floats per k-row, 128 cols * 2)
#define NTHREADS 256

// Scratch: node features after edge layer 0 / 1 (20 MB each)
__device__ float g_h1[N_NODES * L_DIM];
__device__ float g_h2[N_NODES * L_DIM];

__global__ void zero_kernel(float* __restrict__ p, int n) {
    int i = blockIdx.x * blockDim.x + threadIdx.x;
    int stride = gridDim.x * blockDim.x;
    for (; i < n; i += stride) p[i] = 0.f;
}

// ---- packed fp32x2 helpers (Blackwell FFMA2, PTX-only) ----
__device__ __forceinline__ uint64_t f32x2_fma(uint64_t a, uint64_t b, uint64_t c) {
    uint64_t d;
    asm("fma.rn.f32x2 %0, %1, %2, %3;" : "=l"(d) : "l"(a), "l"(b), "l"(c));
    return d;
}
__device__ __forceinline__ void f32x2_unpack(uint64_t v, float& x, float& y) {
    asm("mov.b64 {%0, %1}, %2;" : "=f"(x), "=f"(y) : "l"(v));
}
__device__ __forceinline__ uint64_t f32x2_pack(float x, float y) {
    uint64_t r;
    asm("mov.b64 %0, {%1, %2};" : "=l"(r) : "f"(x), "f"(y));
    return r;
}
__device__ __forceinline__ uint64_t lds64(const float* p) {
    return *reinterpret_cast<const uint64_t*>(p);
}

// One [64 x NCOLS] GEMM tile on transposed activations:
//   DsT[c][e] = act( sum_k AsT[k][e] * W[k][c] + bias[c] )
// AsT pitch ATP, edge PAIRS contiguous -> A operand = one LDS.64 (two edges).
// W staged per K-chunk into smem DUPLICATED ((w,w) 64-bit) -> B operand =
// one LDS.64. Microtile: 4 edge-pairs x 4 cols of f32x2 accumulators.
template<int KCHUNKS, int KTRUE, int NCOLS, bool RELU, bool TO_GLOBAL>
__device__ __forceinline__ void gemm_tile(
    const float* AsT, const float* __restrict__ W, const float* __restrict__ bias,
    float* DsT, float* s_Bd, const int* s_dst, float* OUT)
{
    const int tid = threadIdx.x;
    const int cg = tid >> 3;   // col-quad index 0..31 (cols cg*4 .. cg*4+3)
    const int ep = tid & 7;    // base edge-pair (pairs ep, ep+8, ep+16, ep+24)
    constexpr int NB = (NCOLS + 127) / 128;

    const float* Ab = AsT + 2 * ep;
    const float* Bb = s_Bd + 8 * cg;

    for (int nb = 0; nb < NB; nb++) {
        const int nbase = nb * 128;
        uint64_t acc[4][4];
#pragma unroll
        for (int i = 0; i < 4; i++)
#pragma unroll
            for (int j = 0; j < 4; j++) acc[i][j] = 0ull;

        // prefetch chunk 0 (KC*128 / NTHREADS == 10 values per thread)
        float pre[10];
#pragma unroll
        for (int r = 0; r < 10; r++) {
            int idx = tid + r * NTHREADS;
            int kk = idx >> 7, c = idx & 127;
            int col = nbase + c;
            pre[r] = (kk < KTRUE && col < NCOLS) ? W[kk * NCOLS + col] : 0.f;
        }

        for (int kc = 0; kc < KCHUNKS; kc++) {
            __syncthreads();   // s_Bd free (previous chunk consumed)
#pragma unroll
            for (int r = 0; r < 10; r++) {
                int idx = tid + r * NTHREADS;
                int kk = idx >> 7, c = idx & 127;
                *reinterpret_cast<uint64_t*>(s_Bd + kk * BPD + 2 * c) =
                    f32x2_pack(pre[r], pre[r]);
            }
            // prefetch next chunk while computing this one
            if (kc + 1 < KCHUNKS) {
#pragma unroll
                for (int r = 0; r < 10; r++) {
                    int idx = tid + r * NTHREADS;
                    int kk = idx >> 7, c = idx & 127;
                    int k = (kc + 1) * KC + kk, col = nbase + c;
                    pre[r] = (k < KTRUE && col < NCOLS) ? W[k * NCOLS + col] : 0.f;
                }
            }
            __syncthreads();   // s_Bd ready

            const float* Arow = Ab + kc * KC * ATP;
#pragma unroll
            for (int kk = 0; kk < KC; kk++) {
                uint64_t a0 = lds64(Arow + kk * ATP + 0);
                uint64_t a1 = lds64(Arow + kk * ATP + 16);
                uint64_t a2 = lds64(Arow + kk * ATP + 32);
                uint64_t a3 = lds64(Arow + kk * ATP + 48);
                uint64_t b0 = lds64(Bb + kk * BPD + 0);
                uint64_t b1 = lds64(Bb + kk * BPD + 2);
                uint64_t b2 = lds64(Bb + kk * BPD + 4);
                uint64_t b3 = lds64(Bb + kk * BPD + 6);
                acc[0][0] = f32x2_fma(a0, b0, acc[0][0]);
                acc[0][1] = f32x2_fma(a0, b1, acc[0][1]);
                acc[0][2] = f32x2_fma(a0, b2, acc[0][2]);
                acc[0][3] = f32x2_fma(a0, b3, acc[0][3]);
                acc[1][0] = f32x2_fma(a1, b0, acc[1][0]);
                acc[1][1] = f32x2_fma(a1, b1, acc[1][1]);
                acc[1][2] = f32x2_fma(a1, b2, acc[1][2]);
                acc[1][3] = f32x2_fma(a1, b3, acc[1][3]);
                acc[2][0] = f32x2_fma(a2, b0, acc[2][0]);
                acc[2][1] = f32x2_fma(a2, b1, acc[2][1]);
                acc[2][2] = f32x2_fma(a2, b2, acc[2][2]);
                acc[2][3] = f32x2_fma(a2, b3, acc[2][3]);
                acc[3][0] = f32x2_fma(a3, b0, acc[3][0]);
                acc[3][1] = f32x2_fma(a3, b1, acc[3][1]);
                acc[3][2] = f32x2_fma(a3, b2, acc[3][2]);
                acc[3][3] = f32x2_fma(a3, b3, acc[3][3]);
            }
        }
        // epilogue
#pragma unroll
        for (int j = 0; j < 4; j++) {
            int c = nbase + cg * 4 + j;
            if (c < NCOLS) {
                float bc = bias[c];
#pragma unroll
                for (int i = 0; i < 4; i++) {
                    float v0, v1;
                    f32x2_unpack(acc[i][j], v0, v1);
                    v0 += bc; v1 += bc;
                    if (RELU || TO_GLOBAL) { v0 = fmaxf(v0, 0.f); v1 = fmaxf(v1, 0.f); }
                    int e = 2 * (ep + 8 * i);
                    if (TO_GLOBAL) {
                        // relu(segment_max) == atomicMax over clamped msgs into
                        // zero-init buffer; nonneg float order == int order.
                        atomicMax(reinterpret_cast<int*>(OUT) + s_dst[e]     * NCOLS + c, __float_as_int(v0));
                        atomicMax(reinterpret_cast<int*>(OUT) + s_dst[e + 1] * NCOLS + c, __float_as_int(v1));
                    } else {
                        *reinterpret_cast<uint64_t*>(DsT + c * ATP + e) = f32x2_pack(v0, v1);
                    }
                }
            }
        }
    }
}

// Fused per-edge MLP: gather [x_i, x_j - x_i] (transposed) -> 2*CIN -> 300
// -> 300 -> 100 -> clamped scatter-max into OUT[dst].
template<int CIN>
__global__ void __launch_bounds__(NTHREADS, 1)
edge_mlp_kernel(const float* __restrict__ X,
                const int* __restrict__ src, const int* __restrict__ dst,
                const float* __restrict__ W1, const float* __restrict__ B1,
                const float* __restrict__ W2, const float* __restrict__ B2,
                const float* __restrict__ W3, const float* __restrict__ B3,
                float* __restrict__ OUT)
{
    constexpr int KIN  = 2 * CIN;
    constexpr int KCH1 = (KIN + KC - 1) / KC;

    extern __shared__ float smem[];
    float* s_uT  = smem;                    // [300][68] transposed act (in / h2)
    float* s_h1T = smem + H_DIM * ATP;      // [300][68] transposed h1
    float* s_Bd  = smem + 2 * H_DIM * ATP;  // [KC][260] duplicated weight chunk
    int* s_src   = (int*)(s_Bd + KC * BPD);
    int* s_dst   = s_src + TE;

    const int tid = threadIdx.x;
    const int e0  = blockIdx.x * TE;        // grid is exact: 6250*64 == E_EDGES

    if (tid < TE) {
        s_src[tid] = src[e0 + tid];
        s_dst[tid] = dst[e0 + tid];
    }
    __syncthreads();

    // gather transposed: s_uT[k][e] = x_i[k], s_uT[CIN+k][e] = x_j[k]-x_i[k]
    if (CIN % 4 == 0) {
        constexpr int QC = CIN / 4;
        for (int idx = tid; idx < TE * QC; idx += NTHREADS) {
            int e = idx & (TE - 1), kq = idx >> 6;
            float4 xi = *(const float4*)(X + (int64_t)s_dst[e] * CIN + 4 * kq);
            float4 xj = *(const float4*)(X + (int64_t)s_src[e] * CIN + 4 * kq);
            s_uT[(4 * kq + 0) * ATP + e] = xi.x;
            s_uT[(4 * kq + 1) * ATP + e] = xi.y;
            s_uT[(4 * kq + 2) * ATP + e] = xi.z;
            s_uT[(4 * kq + 3) * ATP + e] = xi.w;
            s_uT[(CIN + 4 * kq + 0) * ATP + e] = xj.x - xi.x;
            s_uT[(CIN + 4 * kq + 1) * ATP + e] = xj.y - xi.y;
            s_uT[(CIN + 4 * kq + 2) * ATP + e] = xj.z - xi.z;
            s_uT[(CIN + 4 * kq + 3) * ATP + e] = xj.w - xi.w;
        }
    } else {
        for (int idx = tid; idx < TE * CIN; idx += NTHREADS) {
            int e = idx & (TE - 1), k = idx >> 6;
            float xi = X[(int64_t)s_dst[e] * CIN + k];
            float xj = X[(int64_t)s_src[e] * CIN + k];
            s_uT[k * ATP + e] = xi;
            s_uT[(CIN + k) * ATP + e] = xj - xi;
        }
    }
    // (gemm_tile's leading __syncthreads orders the gather writes)

    gemm_tile<KCH1, KIN, H_DIM, true, false>(s_uT,  W1, B1, s_h1T, s_Bd, s_dst, nullptr);
    gemm_tile<H_DIM / KC, H_DIM, H_DIM, true, false>(s_h1T, W2, B2, s_uT, s_Bd, s_dst, nullptr);
    gemm_tile<H_DIM / KC, H_DIM, L_DIM, false, true>(s_uT,  W3, B3, nullptr, s_Bd, s_dst, OUT);
}

// One block per graph: contiguous segment (batch is sorted) -> add/mean/max
// pooling -> 302 -> 100 -> 100 -> 2 MLP.
__global__ void pool_mlp_kernel(const float* __restrict__ H2,
                                const int* __restrict__ batch,
                                const float* __restrict__ u,
                                const float* __restrict__ w1, const float* __restrict__ b1,
                                const float* __restrict__ w2, const float* __restrict__ b2,
                                const float* __restrict__ w3, const float* __restrict__ b3,
                                float* __restrict__ out)
{
    const int g = blockIdx.x;
    const int t = threadIdx.x;
    __shared__ float p[304];
    __shared__ float q1[100];
    __shared__ float q2[100];

    int s, e2;
    { int a = 0, b = N_NODES; while (a < b) { int m = (a + b) >> 1; if (batch[m] < g) a = m + 1; else b = m; } s = a; }
    { int a = 0, b = N_NODES; while (a < b) { int m = (a + b) >> 1; if (batch[m] < g + 1) a = m + 1; else b = m; } e2 = a; }
    int cnt = e2 - s;

    if (t < L_DIM) {
        float sm = 0.f, mx = 0.f;
        for (int i = s; i < e2; i++) {
            float v = H2[i * L_DIM + t];
            sm += v;
            mx = fmaxf(mx, v);
        }
        p[t] = sm;
        p[L_DIM + t] = sm / fmaxf((float)cnt, 1.0f);
        p[2 * L_DIM + t] = (cnt > 0) ? mx : 0.f;
    }
    if (t < 2) p[3 * L_DIM + t] = u[g * 2 + t];
    __syncthreads();

    if (t < L_DIM) {
        float acc = b1[t];
        for (int k = 0; k < 3 * L_DIM + 2; k++) acc = fmaf(p[k], w1[k * L_DIM + t], acc);
        q1[t] = fmaxf(acc, 0.f);
    }
    __syncthreads();
    if (t < L_DIM) {
        float acc = b2[t];
        for (int k = 0; k < L_DIM; k++) acc = fmaf(q1[k], w2[k * L_DIM + t], acc);
        q2[t] = fmaxf(acc, 0.f);
    }
    __syncthreads();
    if (t < 2) {
        float acc = b3[t];
        for (int k = 0; k < L_DIM; k++) acc = fmaf(q2[k], w3[k * 2 + t], acc);
        out[g * 2 + t] = acc;
    }
}

extern "C" void kernel_launch(void* const* d_in, const int* in_sizes, int n_in,
                              void* d_out, int out_size)
{
    const float* x     = (const float*)d_in[0];
    const int*   ei    = (const int*)d_in[1];
    const int*   batch = (const int*)d_in[2];
    const float* u     = (const float*)d_in[3];
    const float* l0w1  = (const float*)d_in[4];
    const float* l0b1  = (const float*)d_in[5];
    const float* l0w2  = (const float*)d_in[6];
    const float* l0b2  = (const float*)d_in[7];
    const float* l0w3  = (const float*)d_in[8];
    const float* l0b3  = (const float*)d_in[9];
    const float* l1w1  = (const float*)d_in[10];
    const float* l1b1  = (const float*)d_in[11];
    const float* l1w2  = (const float*)d_in[12];
    const float* l1b2  = (const float*)d_in[13];
    const float* l1w3  = (const float*)d_in[14];
    const float* l1b3  = (const float*)d_in[15];
    const float* lw1   = (const float*)d_in[16];
    const float* lb1   = (const float*)d_in[17];
    const float* lw2   = (const float*)d_in[18];
    const float* lb2   = (const float*)d_in[19];
    const float* lw3   = (const float*)d_in[20];
    const float* lb3   = (const float*)d_in[21];
    float* out = (float*)d_out;

    const int* src = ei;
    const int* dst = ei + E_EDGES;

    float *h1p, *h2p;
    cudaGetSymbolAddress((void**)&h1p, g_h1);
    cudaGetSymbolAddress((void**)&h2p, g_h2);

    const int smem_bytes = (2 * H_DIM * ATP + KC * BPD) * (int)sizeof(float)
                         + 2 * TE * (int)sizeof(int);
    cudaFuncSetAttribute(edge_mlp_kernel<7>,   cudaFuncAttributeMaxDynamicSharedMemorySize, smem_bytes);
    cudaFuncSetAttribute(edge_mlp_kernel<100>, cudaFuncAttributeMaxDynamicSharedMemorySize, smem_bytes);

    zero_kernel<<<304, 256>>>(h1p, N_NODES * L_DIM);
    zero_kernel<<<304, 256>>>(h2p, N_NODES * L_DIM);

    const int nblk = E_EDGES / TE;   // exact
    edge_mlp_kernel<7><<<nblk, NTHREADS, smem_bytes>>>(
        x, src, dst, l0w1, l0b1, l0w2, l0b2, l0w3, l0b3, h1p);
    edge_mlp_kernel<100><<<nblk, NTHREADS, smem_bytes>>>(
        h1p, src, dst, l1w1, l1b1, l1w2, l1b2, l1w3, l1b3, h2p);
    pool_mlp_kernel<<<G_GRAPHS, 128>>>(
        h2p, batch, u, lw1, lb1, lw2, lb2, lw3, lb3, out);
}